// round 4
// baseline (speedup 1.0000x reference)
#include <cuda_runtime.h>

// ---------------- problem constants (fixed for this dataset) ----------------
#define Zl    384
#define MBr   46
#define DEGc  7
#define NBc   68
#define BEe   (MBr*DEGc)      // 322 base edges
#define NLD   (NBc*Zl)        // 26112 variable nodes
#define MCK   (MBr*Zl)        // 17664 check nodes
#define EDG   (BEe*Zl)        // 123648 edges
#define BATCH 128
#define B4    32              // batch in float4 units
#define KI    8448            // info bits out
#define NIN   25344           // received LLRs per batch row
#define NITER 20
#define LLRMAX 20.0f

// ---------------- static device scratch (no allocations allowed) ------------
__device__ float4   g_mvc[EDG*B4];      // VN->CN messages  63.3MB
__device__ float4   g_mcv[EDG*B4];      // CN->VN messages  63.3MB
__device__ float4   g_x[NLD*B4];        // final VN totals  13.4MB
__device__ float4   g_lch[NLD*B4];      // channel LLR (-clip) 13.4MB
__device__ unsigned g_bec[BEe];         // per base-edge: (c<<10)|shift
__device__ unsigned g_colptr[NBc+1];    // CSR over base columns
__device__ unsigned g_colent[BEe];      // (base_edge<<10)|shift

// ---------------- graph decode + CSR build (once per launch) ----------------
__global__ void k_build(const int* __restrict__ col) {
    int t = threadIdx.x;
    if (t < BEe) {
        int val = col[t * Zl];          // i=0 edge of this base-edge block
        g_bec[t] = ((unsigned)(val / Zl) << 10) | (unsigned)(val % Zl);
    }
    __syncthreads();
    if (t == 0) {
        unsigned cnt[NBc];
        for (int c = 0; c < NBc; c++) cnt[c] = 0;
        for (int e = 0; e < BEe; e++) cnt[g_bec[e] >> 10]++;
        unsigned run = 0;
        for (int c = 0; c < NBc; c++) { g_colptr[c] = run; run += cnt[c]; }
        g_colptr[NBc] = run;
        unsigned pos[NBc];
        for (int c = 0; c < NBc; c++) pos[c] = 0;
        for (int e = 0; e < BEe; e++) {
            unsigned c = g_bec[e] >> 10;
            g_colent[g_colptr[c] + pos[c]++] = ((unsigned)e << 10) | (g_bec[e] & 1023u);
        }
    }
}

// zero the punctured region of g_lch (first 2*Z variable nodes)
__global__ void k_zero() {
    int t = blockIdx.x * blockDim.x + threadIdx.x;   // 384*256 = 98304 = 768*128
    ((float*)g_lch)[t] = 0.0f;
}

// transpose + clip + negate channel LLRs: lch[(768+n)*128+b] = -clip(llr[b*NIN+n])
__global__ void k_lch(const float* __restrict__ llr) {
    __shared__ float tile[32][33];
    int n0 = blockIdx.x * 32, b0 = blockIdx.y * 32;
    int tx = threadIdx.x, ty = threadIdx.y;          // block (32, 8)
    float* lch = (float*)g_lch;
#pragma unroll
    for (int k = 0; k < 4; k++)
        tile[ty + k*8][tx] = llr[(size_t)(b0 + ty + k*8) * NIN + (n0 + tx)];
    __syncthreads();
#pragma unroll
    for (int k = 0; k < 4; k++) {
        float v = tile[tx][ty + k*8];
        v = fminf(fmaxf(v, -LLRMAX), LLRMAX);
        lch[(size_t)(768 + n0 + ty + k*8) * BATCH + (b0 + tx)] = -v;
    }
}

// ---------------- check-node update (min-sum, exclude-self) -----------------
// Branchless. Tie handling matches reference first-argmin exactly: on a tie
// m2 == m1, so (mag==m1 ? m2 : m1) gives the same value either way.
#define CNCOMP(F)                                                              \
    {                                                                          \
        float m1 = fabsf(v[0].F), m2 = 1e30f;                                  \
        unsigned par = __float_as_uint(v[0].F);                                \
        _Pragma("unroll")                                                      \
        for (int d = 1; d < DEGc; d++) {                                       \
            float mag = fabsf(v[d].F);                                         \
            m2 = fminf(m2, fmaxf(m1, mag));                                    \
            m1 = fminf(m1, mag);                                               \
            par ^= __float_as_uint(v[d].F);                                    \
        }                                                                      \
        par &= 0x80000000u;                                                    \
        _Pragma("unroll")                                                      \
        for (int d = 0; d < DEGc; d++) {                                       \
            unsigned bits = __float_as_uint(v[d].F);                           \
            float mag = fabsf(v[d].F);                                         \
            float sel = (mag == m1) ? m2 : m1;                                 \
            unsigned s = (par ^ bits) & 0x80000000u;                           \
            v[d].F = __uint_as_float(__float_as_uint(sel) | s);                \
        }                                                                      \
    }

template<bool FIRST>
__global__ void __launch_bounds__(256) k_cn() {
    int tid = blockIdx.x * 256 + threadIdx.x;    // MCK*B4 = 565248 = 2208*256
    int b4 = tid & 31;                           // lane = batch slot
    int m  = tid >> 5;                           // check index (warp-uniform)
    int r  = m / Zl;
    int i  = m - r * Zl;
    int beb  = r * DEGc;
    int base = (beb * Zl + i) * B4 + b4;

    float4 v[DEGc];
    if (FIRST) {
        // iteration 0: m_cv == 0 so m_vc == lch[col]; gather channel LLRs
#pragma unroll
        for (int d = 0; d < DEGc; d++) {
            unsigned u = g_bec[beb + d];
            int c  = (int)(u >> 10);
            int sh = (int)(u & 1023u);
            int iv = i + sh; if (iv >= Zl) iv -= Zl;
            v[d] = __ldg(&g_lch[(c * Zl + iv) * B4 + b4]);
        }
    } else {
        // steady state: m_vc stored contiguously by the VN kernel
#pragma unroll
        for (int d = 0; d < DEGc; d++)
            v[d] = g_mvc[base + d * (Zl * B4)];
    }

    CNCOMP(x) CNCOMP(y) CNCOMP(z) CNCOMP(w)

#pragma unroll
    for (int d = 0; d < DEGc; d++)
        g_mcv[base + d * (Zl * B4)] = v[d];
}

// ---------------- variable-node update: emit m_vc = acc - m_cv per edge -----
template<bool LAST>
__global__ void __launch_bounds__(256) k_vn() {
    int tid = blockIdx.x * 256 + threadIdx.x;    // NLD*B4 = 835584 = 3264*256
    int b4 = tid & 31;
    int v  = tid >> 5;
    int c  = v / Zl;
    int i  = v - c * Zl;
    float4 acc = g_lch[v * B4 + b4];
    unsigned j0 = g_colptr[c], j1 = g_colptr[c + 1];
    // pass 1: accumulate total
    for (unsigned j = j0; j < j1; j++) {
        unsigned u = g_colent[j];
        int be = (int)(u >> 10);
        int sh = (int)(u & 1023u);
        int ic = i - sh; if (ic < 0) ic += Zl;
        float4 t = __ldg(&g_mcv[(be * Zl + ic) * B4 + b4]);
        acc.x += t.x; acc.y += t.y; acc.z += t.z; acc.w += t.w;
    }
    if (LAST) {
        g_x[v * B4 + b4] = acc;
    } else {
        // pass 2: reload (L1-hot) and emit extrinsic VN->CN messages
        for (unsigned j = j0; j < j1; j++) {
            unsigned u = g_colent[j];
            int be = (int)(u >> 10);
            int sh = (int)(u & 1023u);
            int ic = i - sh; if (ic < 0) ic += Zl;
            int idx = (be * Zl + ic) * B4 + b4;
            float4 t = __ldg(&g_mcv[idx]);
            g_mvc[idx] = make_float4(acc.x - t.x, acc.y - t.y,
                                     acc.z - t.z, acc.w - t.w);
        }
    }
}

// ---------------- output: out[b*K+n] = -x[n*128+b], n<K ---------------------
__global__ void k_out(float* __restrict__ out) {
    __shared__ float tile[32][33];
    const float* xf = (const float*)g_x;
    int n0 = blockIdx.x * 32, b0 = blockIdx.y * 32;
    int tx = threadIdx.x, ty = threadIdx.y;      // block (32, 8)
#pragma unroll
    for (int k = 0; k < 4; k++)
        tile[ty + k*8][tx] = xf[(size_t)(n0 + ty + k*8) * BATCH + (b0 + tx)];
    __syncthreads();
#pragma unroll
    for (int k = 0; k < 4; k++)
        out[(size_t)(b0 + ty + k*8) * KI + (n0 + tx)] = -tile[tx][ty + k*8];
}

// ---------------- launch ----------------------------------------------------
extern "C" void kernel_launch(void* const* d_in, const int* in_sizes, int n_in,
                              void* d_out, int out_size) {
    const float* llr = (const float*)d_in[0];
    const int*   col = (const int*)d_in[2];

    k_build<<<1, 512>>>(col);
    k_zero<<<384, 256>>>();
    {
        dim3 g(NIN / 32, BATCH / 32), b(32, 8);
        k_lch<<<g, b>>>(llr);
    }
    k_cn<true><<<(MCK * B4) / 256, 256>>>();
    k_vn<false><<<(NLD * B4) / 256, 256>>>();
    for (int it = 1; it < NITER - 1; it++) {
        k_cn<false><<<(MCK * B4) / 256, 256>>>();
        k_vn<false><<<(NLD * B4) / 256, 256>>>();
    }
    k_cn<false><<<(MCK * B4) / 256, 256>>>();
    k_vn<true><<<(NLD * B4) / 256, 256>>>();
    {
        dim3 g(KI / 32, BATCH / 32), b(32, 8);
        k_out<<<g, b>>>((float*)d_out);
    }
}

// round 6
// speedup vs baseline: 1.4160x; 1.4160x over previous
#include <cuda_runtime.h>

// ---------------- problem constants (fixed for this dataset) ----------------
#define Zl    384
#define MBr   46
#define DEGc  7
#define NBc   68
#define BEe   (MBr*DEGc)      // 322 base edges
#define NLD   (NBc*Zl)        // 26112 variable nodes
#define MCK   (MBr*Zl)        // 17664 check nodes
#define EDG   (BEe*Zl)        // 123648 edges
#define BATCH 128
#define B4    32              // batch in float4 units
#define KI    8448            // info bits out
#define NIN   25344           // received LLRs per batch row
#define NITER 20
#define LLRMAX 20.0f

// ---------------- static device scratch (no allocations allowed) ------------
// Single in-place edge message buffer: holds m_vc before k_cn, m_cv after.
// Footprint: 63.3 + 13.4 + 13.4 = ~90MB  -> resident in 126MB L2.
__device__ float4   g_msg[EDG*B4];      // edge messages (in-place)  63.3MB
__device__ float4   g_x[NLD*B4];        // final VN totals           13.4MB
__device__ float4   g_lch[NLD*B4];      // channel LLR (-clip)       13.4MB
__device__ unsigned g_bec[BEe];         // per base-edge: (c<<10)|shift
__device__ unsigned g_colptr[NBc+1];    // CSR over base columns
__device__ unsigned g_colent[BEe];      // (base_edge<<10)|shift

// ---------------- graph decode + CSR build (once per launch) ----------------
__global__ void k_build(const int* __restrict__ col) {
    int t = threadIdx.x;
    if (t < BEe) {
        int val = col[t * Zl];          // i=0 edge of this base-edge block
        g_bec[t] = ((unsigned)(val / Zl) << 10) | (unsigned)(val % Zl);
    }
    __syncthreads();
    if (t == 0) {
        unsigned cnt[NBc];
        for (int c = 0; c < NBc; c++) cnt[c] = 0;
        for (int e = 0; e < BEe; e++) cnt[g_bec[e] >> 10]++;
        unsigned run = 0;
        for (int c = 0; c < NBc; c++) { g_colptr[c] = run; run += cnt[c]; }
        g_colptr[NBc] = run;
        unsigned pos[NBc];
        for (int c = 0; c < NBc; c++) pos[c] = 0;
        for (int e = 0; e < BEe; e++) {
            unsigned c = g_bec[e] >> 10;
            g_colent[g_colptr[c] + pos[c]++] = ((unsigned)e << 10) | (g_bec[e] & 1023u);
        }
    }
}

// zero the punctured region of g_lch (first 2*Z variable nodes)
__global__ void k_zero() {
    int t = blockIdx.x * blockDim.x + threadIdx.x;   // 384*256 = 98304 = 768*128
    ((float*)g_lch)[t] = 0.0f;
}

// transpose + clip + negate channel LLRs: lch[(768+n)*128+b] = -clip(llr[b*NIN+n])
__global__ void k_lch(const float* __restrict__ llr) {
    __shared__ float tile[32][33];
    int n0 = blockIdx.x * 32, b0 = blockIdx.y * 32;
    int tx = threadIdx.x, ty = threadIdx.y;          // block (32, 8)
    float* lch = (float*)g_lch;
#pragma unroll
    for (int k = 0; k < 4; k++)
        tile[ty + k*8][tx] = llr[(size_t)(b0 + ty + k*8) * NIN + (n0 + tx)];
    __syncthreads();
#pragma unroll
    for (int k = 0; k < 4; k++) {
        float v = tile[tx][ty + k*8];
        v = fminf(fmaxf(v, -LLRMAX), LLRMAX);
        lch[(size_t)(768 + n0 + ty + k*8) * BATCH + (b0 + tx)] = -v;
    }
}

// ---------------- check-node update (min-sum, exclude-self) -----------------
// Branchless. Tie handling matches reference first-argmin exactly: on a tie
// m2 == m1, so (mag==m1 ? m2 : m1) gives the same value either way.
#define CNCOMP(F)                                                              \
    {                                                                          \
        float m1 = fabsf(v[0].F), m2 = 1e30f;                                  \
        unsigned par = __float_as_uint(v[0].F);                                \
        _Pragma("unroll")                                                      \
        for (int d = 1; d < DEGc; d++) {                                       \
            float mag = fabsf(v[d].F);                                         \
            m2 = fminf(m2, fmaxf(m1, mag));                                    \
            m1 = fminf(m1, mag);                                               \
            par ^= __float_as_uint(v[d].F);                                    \
        }                                                                      \
        par &= 0x80000000u;                                                    \
        _Pragma("unroll")                                                      \
        for (int d = 0; d < DEGc; d++) {                                       \
            unsigned bits = __float_as_uint(v[d].F);                           \
            float mag = fabsf(v[d].F);                                         \
            float sel = (mag == m1) ? m2 : m1;                                 \
            unsigned s = (par ^ bits) & 0x80000000u;                           \
            v[d].F = __uint_as_float(__float_as_uint(sel) | s);                \
        }                                                                      \
    }

template<bool FIRST>
__global__ void __launch_bounds__(256) k_cn() {
    int tid = blockIdx.x * 256 + threadIdx.x;    // MCK*B4 = 565248 = 2208*256
    int b4 = tid & 31;                           // lane = batch slot
    int m  = tid >> 5;                           // check index (warp-uniform)
    int r  = m / Zl;
    int i  = m - r * Zl;
    int beb  = r * DEGc;
    int base = (beb * Zl + i) * B4 + b4;

    float4 v[DEGc];
    if (FIRST) {
        // iteration 0: m_cv == 0 so m_vc == lch[col]; gather channel LLRs
#pragma unroll
        for (int d = 0; d < DEGc; d++) {
            unsigned u = g_bec[beb + d];
            int c  = (int)(u >> 10);
            int sh = (int)(u & 1023u);
            int iv = i + sh; if (iv >= Zl) iv -= Zl;
            v[d] = __ldg(&g_lch[(c * Zl + iv) * B4 + b4]);
        }
    } else {
        // steady state: m_vc stored contiguously (in place) by the VN kernel
#pragma unroll
        for (int d = 0; d < DEGc; d++)
            v[d] = g_msg[base + d * (Zl * B4)];
    }

    CNCOMP(x) CNCOMP(y) CNCOMP(z) CNCOMP(w)

    // in-place overwrite: buffer now holds m_cv
#pragma unroll
    for (int d = 0; d < DEGc; d++)
        g_msg[base + d * (Zl * B4)] = v[d];
}

// ---------------- variable-node update: m_vc = acc - m_cv, in place ---------
template<bool LAST>
__global__ void __launch_bounds__(256) k_vn() {
    int tid = blockIdx.x * 256 + threadIdx.x;    // NLD*B4 = 835584 = 3264*256
    int b4 = tid & 31;
    int v  = tid >> 5;
    int c  = v / Zl;
    int i  = v - c * Zl;
    float4 acc = g_lch[v * B4 + b4];
    unsigned j0 = g_colptr[c], j1 = g_colptr[c + 1];
    // pass 1: accumulate total (coalesced 512B per edge per warp)
    for (unsigned j = j0; j < j1; j++) {
        unsigned u = g_colent[j];
        int be = (int)(u >> 10);
        int sh = (int)(u & 1023u);
        int ic = i - sh; if (ic < 0) ic += Zl;
        float4 t = __ldg(&g_msg[(be * Zl + ic) * B4 + b4]);
        acc.x += t.x; acc.y += t.y; acc.z += t.z; acc.w += t.w;
    }
    if (LAST) {
        g_x[v * B4 + b4] = acc;
    } else {
        // pass 2: reload (L1-hot) and overwrite with extrinsic VN->CN messages
        for (unsigned j = j0; j < j1; j++) {
            unsigned u = g_colent[j];
            int be = (int)(u >> 10);
            int sh = (int)(u & 1023u);
            int ic = i - sh; if (ic < 0) ic += Zl;
            int idx = (be * Zl + ic) * B4 + b4;
            float4 t = __ldg(&g_msg[idx]);
            g_msg[idx] = make_float4(acc.x - t.x, acc.y - t.y,
                                     acc.z - t.z, acc.w - t.w);
        }
    }
}

// ---------------- output: out[b*K+n] = -x[n*128+b], n<K ---------------------
__global__ void k_out(float* __restrict__ out) {
    __shared__ float tile[32][33];
    const float* xf = (const float*)g_x;
    int n0 = blockIdx.x * 32, b0 = blockIdx.y * 32;
    int tx = threadIdx.x, ty = threadIdx.y;      // block (32, 8)
#pragma unroll
    for (int k = 0; k < 4; k++)
        tile[ty + k*8][tx] = xf[(size_t)(n0 + ty + k*8) * BATCH + (b0 + tx)];
    __syncthreads();
#pragma unroll
    for (int k = 0; k < 4; k++)
        out[(size_t)(b0 + ty + k*8) * KI + (n0 + tx)] = -tile[tx][ty + k*8];
}

// ---------------- launch ----------------------------------------------------
extern "C" void kernel_launch(void* const* d_in, const int* in_sizes, int n_in,
                              void* d_out, int out_size) {
    const float* llr = (const float*)d_in[0];
    const int*   col = (const int*)d_in[2];

    k_build<<<1, 512>>>(col);
    k_zero<<<384, 256>>>();
    {
        dim3 g(NIN / 32, BATCH / 32), b(32, 8);
        k_lch<<<g, b>>>(llr);
    }
    k_cn<true><<<(MCK * B4) / 256, 256>>>();
    k_vn<false><<<(NLD * B4) / 256, 256>>>();
    for (int it = 1; it < NITER - 1; it++) {
        k_cn<false><<<(MCK * B4) / 256, 256>>>();
        k_vn<false><<<(NLD * B4) / 256, 256>>>();
    }
    k_cn<false><<<(MCK * B4) / 256, 256>>>();
    k_vn<true><<<(NLD * B4) / 256, 256>>>();
    {
        dim3 g(KI / 32, BATCH / 32), b(32, 8);
        k_out<<<g, b>>>((float*)d_out);
    }
}